// round 2
// baseline (speedup 1.0000x reference)
#include <cuda_runtime.h>
#include <math.h>

#define M_ANCH   589824
#define NCLS     80
#define K_TOP    1000
#define CAND_CAP 4096
#define NBINS    2048
#define IMG_INV  (1.0f/2048.0f)
#define SCALE_CLAMP 4.1351665567423560f   /* log(1000/16) */

// ---------------- scratch (device globals; no allocations allowed) ----------
__device__ unsigned            g_key[M_ANCH];
__device__ unsigned            g_hist1[NBINS];
__device__ unsigned            g_hist2[NBINS];
__device__ unsigned            g_B1;
__device__ unsigned            g_cntAbove1;
__device__ unsigned            g_thresh;
__device__ unsigned            g_candCount;
__device__ unsigned long long  g_cand[CAND_CAP];
__device__ int                 g_selIdx[K_TOP];
__device__ float4              g_boxes[K_TOP];
__device__ int                 g_labels[K_TOP];
__device__ int                 g_valid[K_TOP];
__device__ unsigned            g_mask[K_TOP * 32];

// ---------------- helpers ---------------------------------------------------
__device__ __forceinline__ unsigned f2ord(float f) {
    unsigned u = __float_as_uint(f);
    return (u & 0x80000000u) ? ~u : (u | 0x80000000u);
}
__device__ __forceinline__ float ord2f(unsigned o) {
    return (o & 0x80000000u) ? __uint_as_float(o & 0x7FFFFFFFu)
                             : __uint_as_float(~o);
}
// Sigmoid matching modern XLA lowering of lax.logistic on GPU:
//   1 / (1 + exp(-x)), exp via libdevice (__nv_expf == expf), rn ops, no FMA.
__device__ __forceinline__ float ref_sigmoid(float x) {
    float e = expf(-x);
    return __fdiv_rn(1.0f, __fadd_rn(1.0f, e));
}

// ---------------- kernels ---------------------------------------------------
__global__ void k_init() {
    int t = threadIdx.x;
    g_hist1[t] = 0u; g_hist1[t + 1024] = 0u;
    g_hist2[t] = 0u; g_hist2[t + 1024] = 0u;
    if (t == 0) g_candCount = 0u;
}

// warp per row (8 rows per warp), block = 512 threads (16 warps), grid = 4608
__global__ void k_rowmax(const float* __restrict__ cls) {
    __shared__ unsigned sh[NBINS];
    for (int b = threadIdx.x; b < NBINS; b += blockDim.x) sh[b] = 0u;
    __syncthreads();

    const int warp = threadIdx.x >> 5;
    const int lane = threadIdx.x & 31;
    const int rowBase = (blockIdx.x * 16 + warp) * 8;
    const float NEGINF = __int_as_float(0xff800000);

#pragma unroll
    for (int r = 0; r < 8; r++) {
        int row = rowBase + r;
        const float* p = cls + (size_t)row * NCLS;
        float v0 = p[lane];
        float v1 = p[lane + 32];
        float v2 = (lane < 16) ? p[lane + 64] : NEGINF;
        float m = fmaxf(fmaxf(v0, v1), v2);
        unsigned mk = __reduce_max_sync(0xffffffffu, f2ord(m));
        if (lane == 0) {
            float maxlogit = ord2f(mk);
            unsigned key = f2ord(ref_sigmoid(maxlogit));
            g_key[row] = key;
            atomicAdd(&sh[key >> 21], 1u);
        }
    }
    __syncthreads();
    for (int b = threadIdx.x; b < NBINS; b += blockDim.x) {
        unsigned c = sh[b];
        if (c) atomicAdd(&g_hist1[b], c);
    }
}

// single block, 1024 threads: suffix-scan hist1, find coarse bin B1
__global__ void k_find1() {
    __shared__ unsigned s[NBINS];
    __shared__ int best;
    int t = threadIdx.x;
    s[t] = g_hist1[t]; s[t + 1024] = g_hist1[t + 1024];
    if (t == 0) best = -1;
    __syncthreads();
    for (int off = 1; off < NBINS; off <<= 1) {
        unsigned a = (t + off < NBINS) ? s[t + off] : 0u;
        unsigned b = (t + 1024 + off < NBINS) ? s[t + 1024 + off] : 0u;
        __syncthreads();
        s[t] += a; s[t + 1024] += b;
        __syncthreads();
    }
    if (s[t] >= K_TOP)        atomicMax(&best, t);
    if (s[t + 1024] >= K_TOP) atomicMax(&best, t + 1024);
    __syncthreads();
    if (t == 0) {
        g_B1 = (unsigned)best;
        g_cntAbove1 = (best < NBINS - 1) ? s[best + 1] : 0u;
    }
}

// grid 576 x 1024 (one key each): histogram of mid-11-bits within bin B1
__global__ void k_hist2() {
    __shared__ unsigned sh[NBINS];
    int t = threadIdx.x;
    sh[t] = 0u; sh[t + 1024] = 0u;
    __syncthreads();
    unsigned B1 = g_B1;
    unsigned key = g_key[blockIdx.x * 1024 + t];
    if ((key >> 21) == B1) atomicAdd(&sh[(key >> 10) & 2047u], 1u);
    __syncthreads();
    unsigned c0 = sh[t], c1 = sh[t + 1024];
    if (c0) atomicAdd(&g_hist2[t], c0);
    if (c1) atomicAdd(&g_hist2[t + 1024], c1);
}

__global__ void k_find2() {
    __shared__ unsigned s[NBINS];
    __shared__ int best;
    int t = threadIdx.x;
    s[t] = g_hist2[t]; s[t + 1024] = g_hist2[t + 1024];
    if (t == 0) best = -1;
    __syncthreads();
    for (int off = 1; off < NBINS; off <<= 1) {
        unsigned a = (t + off < NBINS) ? s[t + off] : 0u;
        unsigned b = (t + 1024 + off < NBINS) ? s[t + 1024 + off] : 0u;
        __syncthreads();
        s[t] += a; s[t + 1024] += b;
        __syncthreads();
    }
    unsigned base = g_cntAbove1;
    if (base + s[t] >= K_TOP)        atomicMax(&best, t);
    if (base + s[t + 1024] >= K_TOP) atomicMax(&best, t + 1024);
    __syncthreads();
    if (t == 0) g_thresh = (g_B1 << 21) | ((unsigned)best << 10);
}

__global__ void k_compact() {
    int i = blockIdx.x * 1024 + threadIdx.x;
    unsigned key = g_key[i];
    if (key >= g_thresh) {
        unsigned pos = atomicAdd(&g_candCount, 1u);
        if (pos < CAND_CAP)
            g_cand[pos] = ((unsigned long long)key << 32) | (unsigned)(~i);
    }
}

// single block, 1024 threads: bitonic sort 4096 u64 keys ascending
__global__ void k_sort() {
    __shared__ unsigned long long s[CAND_CAP];
    int t = threadIdx.x;
    unsigned cnt = min(g_candCount, (unsigned)CAND_CAP);
#pragma unroll
    for (int e = 0; e < 4; e++) {
        unsigned i = t + e * 1024;
        s[i] = (i < cnt) ? g_cand[i] : 0ULL;
    }
    __syncthreads();
    for (unsigned k = 2; k <= CAND_CAP; k <<= 1) {
        for (unsigned j = k >> 1; j > 0; j >>= 1) {
#pragma unroll
            for (int e = 0; e < 4; e++) {
                unsigned i = t + e * 1024;
                unsigned ixj = i ^ j;
                if (ixj > i) {
                    bool asc = ((i & k) == 0);
                    unsigned long long a = s[i], b = s[ixj];
                    if ((a > b) == asc) { s[i] = b; s[ixj] = a; }
                }
            }
            __syncthreads();
        }
    }
    if (t < K_TOP)
        g_selIdx[t] = (int)(~(unsigned)(s[CAND_CAP - 1 - t] & 0xFFFFFFFFULL));
}

// decode winners: 8 blocks x 128
__global__ void k_decode(const float* __restrict__ cls,
                         const float* __restrict__ reg,
                         const float* __restrict__ anc,
                         float* __restrict__ out) {
    int j = blockIdx.x * 128 + threadIdx.x;
    if (j >= K_TOP) return;
    int i = g_selIdx[j];

    // argmax over sigmoid(probs), first occurrence on ties (matches jnp.argmax)
    const float4* row = (const float4*)(cls + (size_t)i * NCLS);
    float best = -1.0f; int bl = 0;
#pragma unroll
    for (int q = 0; q < NCLS / 4; q++) {
        float4 v = row[q];
        float s0 = ref_sigmoid(v.x), s1 = ref_sigmoid(v.y);
        float s2 = ref_sigmoid(v.z), s3 = ref_sigmoid(v.w);
        if (s0 > best) { best = s0; bl = 4 * q + 0; }
        if (s1 > best) { best = s1; bl = 4 * q + 1; }
        if (s2 > best) { best = s2; bl = 4 * q + 2; }
        if (s3 > best) { best = s3; bl = 4 * q + 3; }
    }

    float4 rg = ((const float4*)reg)[i];
    float4 an = ((const float4*)anc)[i];
    float ox = fminf(fmaxf(rg.x * an.z, -32.0f), 32.0f);
    float oy = fminf(fmaxf(rg.y * an.w, -32.0f), 32.0f);
    float cx = an.x + ox, cy = an.y + oy;
    float w = an.z * expf(fminf(rg.z, SCALE_CLAMP));
    float h = an.w * expf(fminf(rg.w, SCALE_CLAMP));
    float x1 = fminf(fmaxf((cx - 0.5f * w) * IMG_INV, 0.0f), 1.0f);
    float y1 = fminf(fmaxf((cy - 0.5f * h) * IMG_INV, 0.0f), 1.0f);
    float x2 = fminf(fmaxf((cx + 0.5f * w) * IMG_INV, 0.0f), 1.0f);
    float y2 = fminf(fmaxf((cy + 0.5f * h) * IMG_INV, 0.0f), 1.0f);

    out[4 * j + 0] = x1; out[4 * j + 1] = y1;
    out[4 * j + 2] = x2; out[4 * j + 3] = y2;
    out[4000 + j] = best;
    out[5000 + j] = (float)bl;
    g_boxes[j] = make_float4(x1, y1, x2, y2);
    g_labels[j] = bl;
    g_valid[j] = (best >= 0.05f) ? 1 : 0;
}

// suppression bitmask: 1000 blocks x 256 threads; mask[i][w] bit b => j=w*32+b
// suppresses i (iou>0.6, same class, j<i)
__global__ void k_mask() {
    int i = blockIdx.x;
    float4 bi = g_boxes[i];
    int li = g_labels[i];
    float ai = (bi.z - bi.x) * (bi.w - bi.y);
    int lane = threadIdx.x & 31, w0 = threadIdx.x >> 5;
    for (int W = w0; W < 32; W += 8) {
        int j = W * 32 + lane;
        bool sup = false;
        if (j < i) {
            if (g_labels[j] == li) {
                float4 bj = g_boxes[j];
                float xx1 = fmaxf(bi.x, bj.x), yy1 = fmaxf(bi.y, bj.y);
                float xx2 = fminf(bi.z, bj.z), yy2 = fminf(bi.w, bj.w);
                float ww = fmaxf(1e-10f, xx2 - xx1);
                float hh = fmaxf(1e-10f, yy2 - yy1);
                float inter = ww * hh;
                float aj = (bj.z - bj.x) * (bj.w - bj.y);
                float iou = inter / (ai + aj - inter + 1e-10f);
                sup = iou > 0.6f;
            }
        }
        unsigned bits = __ballot_sync(0xffffffffu, sup);
        if (lane == 0) g_mask[i * 32 + W] = bits;
    }
}

// serial greedy NMS: 1 block, mask staged in 128KB dynamic smem, warp 0 runs it
__global__ void k_nms(float* __restrict__ out) {
    extern __shared__ unsigned sm[];
    for (int idx = threadIdx.x; idx < K_TOP * 32; idx += blockDim.x)
        sm[idx] = g_mask[idx];
    __syncthreads();
    if (threadIdx.x >= 32) return;
    int t = threadIdx.x;

    unsigned validw = 0u;
#pragma unroll
    for (int b = 0; b < 32; b++) {
        int j = t * 32 + b;
        if (j < K_TOP && g_valid[j]) validw |= (1u << b);
    }

    unsigned keepw = 0u;
    unsigned cur = sm[t];
    for (int i = 0; i < K_TOP; i++) {
        unsigned nxt = (i < K_TOP - 1) ? sm[(i + 1) * 32 + t] : 0u;
        bool ov = __any_sync(0xffffffffu, (cur & keepw) != 0u);
        int w = i >> 5, b = i & 31;
        unsigned vb = (__shfl_sync(0xffffffffu, validw, w) >> b) & 1u;
        bool kp = (vb != 0u) && !ov;
        if (kp && t == w) keepw |= (1u << b);
        if (t == 0) out[6000 + i] = kp ? 1.0f : 0.0f;
        cur = nxt;
    }
}

// ---------------- launcher ---------------------------------------------------
extern "C" void kernel_launch(void* const* d_in, const int* in_sizes, int n_in,
                              void* d_out, int out_size) {
    const float* cls = (const float*)d_in[0];
    const float* reg = (const float*)d_in[1];
    const float* anc = (const float*)d_in[2];
    float* out = (float*)d_out;

    (void)in_sizes; (void)n_in; (void)out_size;

    cudaFuncSetAttribute(k_nms, cudaFuncAttributeMaxDynamicSharedMemorySize,
                         131072);

    k_init<<<1, 1024>>>();
    k_rowmax<<<4608, 512>>>(cls);
    k_find1<<<1, 1024>>>();
    k_hist2<<<576, 1024>>>();
    k_find2<<<1, 1024>>>();
    k_compact<<<576, 1024>>>();
    k_sort<<<1, 1024>>>();
    k_decode<<<8, 128>>>(cls, reg, anc, out);
    k_mask<<<1000, 256>>>();
    k_nms<<<1, 1024, K_TOP * 32 * sizeof(unsigned)>>>(out);
}

// round 3
// speedup vs baseline: 1.4395x; 1.4395x over previous
#include <cuda_runtime.h>
#include <math.h>

#define M_ANCH   589824
#define NCLS     80
#define K_TOP    1000
#define CAND_CAP 4096
#define NBINS    2048
#define IMG_INV  (1.0f/2048.0f)
#define SCALE_CLAMP 4.1351665567423560f   /* log(1000/16) */

// ---------------- scratch (device globals; no allocations allowed) ----------
__device__ unsigned            g_key[M_ANCH];
__device__ unsigned            g_hist1[NBINS];
__device__ unsigned            g_hist2[NBINS];
__device__ unsigned            g_B1;
__device__ unsigned            g_cntAbove1;
__device__ unsigned            g_thresh;
__device__ unsigned            g_candCount;
__device__ unsigned long long  g_cand[CAND_CAP];
__device__ int                 g_selIdx[K_TOP];
__device__ float4              g_boxes[K_TOP];
__device__ int                 g_labels[K_TOP];
__device__ int                 g_valid[K_TOP];
__device__ unsigned            g_mask[K_TOP * 32];

// ---------------- helpers ---------------------------------------------------
__device__ __forceinline__ unsigned f2ord(float f) {
    unsigned u = __float_as_uint(f);
    return (u & 0x80000000u) ? ~u : (u | 0x80000000u);
}
// Sigmoid matching XLA lowering of lax.logistic on GPU:
//   1 / (1 + exp(-x)), exp via libdevice, rn ops, no FMA contraction.
__device__ __forceinline__ float ref_sigmoid(float x) {
    float e = expf(-x);
    return __fdiv_rn(1.0f, __fadd_rn(1.0f, e));
}

// ---------------- kernels ---------------------------------------------------
__global__ void k_init() {
    int t = threadIdx.x;
    g_hist1[t] = 0u; g_hist1[t + 1024] = 0u;
    g_hist2[t] = 0u; g_hist2[t + 1024] = 0u;
    if (t == 0) g_candCount = 0u;
}

// thread per row: 20 x float4 loads, grid 1152 x 512
__global__ void k_rowmax(const float* __restrict__ cls) {
    __shared__ unsigned sh[NBINS];
    int t = threadIdx.x;
    sh[t] = 0u; sh[t + 512] = 0u; sh[t + 1024] = 0u; sh[t + 1536] = 0u;
    __syncthreads();

    int row = blockIdx.x * 512 + t;
    const float4* p = (const float4*)(cls + (size_t)row * NCLS);
    float m = __int_as_float(0xff800000);
#pragma unroll
    for (int q = 0; q < NCLS / 4; q++) {
        float4 v = p[q];
        m = fmaxf(m, fmaxf(fmaxf(v.x, v.y), fmaxf(v.z, v.w)));
    }
    unsigned key = f2ord(ref_sigmoid(m));
    g_key[row] = key;
    atomicAdd(&sh[key >> 21], 1u);
    __syncthreads();

    unsigned c0 = sh[t], c1 = sh[t + 512], c2 = sh[t + 1024], c3 = sh[t + 1536];
    if (c0) atomicAdd(&g_hist1[t], c0);
    if (c1) atomicAdd(&g_hist1[t + 512], c1);
    if (c2) atomicAdd(&g_hist1[t + 1024], c2);
    if (c3) atomicAdd(&g_hist1[t + 1536], c3);
}

// single block, 1024 threads: suffix-scan hist1, find coarse bin B1
__global__ void k_find1() {
    __shared__ unsigned s[NBINS];
    __shared__ int best;
    int t = threadIdx.x;
    s[t] = g_hist1[t]; s[t + 1024] = g_hist1[t + 1024];
    if (t == 0) best = -1;
    __syncthreads();
    for (int off = 1; off < NBINS; off <<= 1) {
        unsigned a = (t + off < NBINS) ? s[t + off] : 0u;
        unsigned b = (t + 1024 + off < NBINS) ? s[t + 1024 + off] : 0u;
        __syncthreads();
        s[t] += a; s[t + 1024] += b;
        __syncthreads();
    }
    if (s[t] >= K_TOP)        atomicMax(&best, t);
    if (s[t + 1024] >= K_TOP) atomicMax(&best, t + 1024);
    __syncthreads();
    if (t == 0) {
        g_B1 = (unsigned)best;
        g_cntAbove1 = (best < NBINS - 1) ? s[best + 1] : 0u;
    }
}

// grid 288 x 256: each block covers 2048 keys via 2 uint4 loads per thread
__global__ void k_hist2() {
    __shared__ unsigned sh[NBINS];
    int t = threadIdx.x;
#pragma unroll
    for (int e = 0; e < 8; e++) sh[t + e * 256] = 0u;
    __syncthreads();
    unsigned B1 = g_B1;
    const uint4* kp = (const uint4*)g_key;
    int base = blockIdx.x * 512;
#pragma unroll
    for (int e = 0; e < 2; e++) {
        uint4 k4 = kp[base + e * 256 + t];
        if ((k4.x >> 21) == B1) atomicAdd(&sh[(k4.x >> 10) & 2047u], 1u);
        if ((k4.y >> 21) == B1) atomicAdd(&sh[(k4.y >> 10) & 2047u], 1u);
        if ((k4.z >> 21) == B1) atomicAdd(&sh[(k4.z >> 10) & 2047u], 1u);
        if ((k4.w >> 21) == B1) atomicAdd(&sh[(k4.w >> 10) & 2047u], 1u);
    }
    __syncthreads();
#pragma unroll
    for (int e = 0; e < 8; e++) {
        unsigned c = sh[t + e * 256];
        if (c) atomicAdd(&g_hist2[t + e * 256], c);
    }
}

__global__ void k_find2() {
    __shared__ unsigned s[NBINS];
    __shared__ int best;
    int t = threadIdx.x;
    s[t] = g_hist2[t]; s[t + 1024] = g_hist2[t + 1024];
    if (t == 0) best = -1;
    __syncthreads();
    for (int off = 1; off < NBINS; off <<= 1) {
        unsigned a = (t + off < NBINS) ? s[t + off] : 0u;
        unsigned b = (t + 1024 + off < NBINS) ? s[t + 1024 + off] : 0u;
        __syncthreads();
        s[t] += a; s[t + 1024] += b;
        __syncthreads();
    }
    unsigned base = g_cntAbove1;
    if (base + s[t] >= K_TOP)        atomicMax(&best, t);
    if (base + s[t + 1024] >= K_TOP) atomicMax(&best, t + 1024);
    __syncthreads();
    if (t == 0) g_thresh = (g_B1 << 21) | ((unsigned)best << 10);
}

// grid 288 x 256: compact keys >= thresh into g_cand
__global__ void k_compact() {
    unsigned thr = g_thresh;
    const uint4* kp = (const uint4*)g_key;
    int base = blockIdx.x * 512;
    int t = threadIdx.x;
#pragma unroll
    for (int e = 0; e < 2; e++) {
        int i4 = base + e * 256 + t;
        uint4 k4 = kp[i4];
        int i0 = i4 * 4;
        if (k4.x >= thr) {
            unsigned pos = atomicAdd(&g_candCount, 1u);
            if (pos < CAND_CAP)
                g_cand[pos] = ((unsigned long long)k4.x << 32) | (unsigned)(~(i0 + 0));
        }
        if (k4.y >= thr) {
            unsigned pos = atomicAdd(&g_candCount, 1u);
            if (pos < CAND_CAP)
                g_cand[pos] = ((unsigned long long)k4.y << 32) | (unsigned)(~(i0 + 1));
        }
        if (k4.z >= thr) {
            unsigned pos = atomicAdd(&g_candCount, 1u);
            if (pos < CAND_CAP)
                g_cand[pos] = ((unsigned long long)k4.z << 32) | (unsigned)(~(i0 + 2));
        }
        if (k4.w >= thr) {
            unsigned pos = atomicAdd(&g_candCount, 1u);
            if (pos < CAND_CAP)
                g_cand[pos] = ((unsigned long long)k4.w << 32) | (unsigned)(~(i0 + 3));
        }
    }
}

// O(n^2) ranking instead of sort: 8 blocks x 512; keys unique -> unique ranks
__global__ void k_rank() {
    __shared__ unsigned long long s[CAND_CAP];
    unsigned cnt = min(g_candCount, (unsigned)CAND_CAP);
    for (unsigned j = threadIdx.x; j < cnt; j += 512) s[j] = g_cand[j];
    __syncthreads();
    unsigned id = blockIdx.x * 512 + threadIdx.x;
    if (id >= cnt) return;
    unsigned long long my = s[id];
    unsigned rank = 0;
    unsigned j = 0;
    for (; j + 4 <= cnt; j += 4) {
        rank += (s[j]     > my);
        rank += (s[j + 1] > my);
        rank += (s[j + 2] > my);
        rank += (s[j + 3] > my);
    }
    for (; j < cnt; j++) rank += (s[j] > my);
    if (rank < K_TOP)
        g_selIdx[rank] = (int)(~(unsigned)(my & 0xFFFFFFFFULL));
}

// decode winners: 8 blocks x 128
__global__ void k_decode(const float* __restrict__ cls,
                         const float* __restrict__ reg,
                         const float* __restrict__ anc,
                         float* __restrict__ out) {
    int j = blockIdx.x * 128 + threadIdx.x;
    if (j >= K_TOP) return;
    int i = g_selIdx[j];

    const float4* row = (const float4*)(cls + (size_t)i * NCLS);
    float best = -1.0f; int bl = 0;
#pragma unroll
    for (int q = 0; q < NCLS / 4; q++) {
        float4 v = row[q];
        float s0 = ref_sigmoid(v.x), s1 = ref_sigmoid(v.y);
        float s2 = ref_sigmoid(v.z), s3 = ref_sigmoid(v.w);
        if (s0 > best) { best = s0; bl = 4 * q + 0; }
        if (s1 > best) { best = s1; bl = 4 * q + 1; }
        if (s2 > best) { best = s2; bl = 4 * q + 2; }
        if (s3 > best) { best = s3; bl = 4 * q + 3; }
    }

    float4 rg = ((const float4*)reg)[i];
    float4 an = ((const float4*)anc)[i];
    float ox = fminf(fmaxf(rg.x * an.z, -32.0f), 32.0f);
    float oy = fminf(fmaxf(rg.y * an.w, -32.0f), 32.0f);
    float cx = an.x + ox, cy = an.y + oy;
    float w = an.z * expf(fminf(rg.z, SCALE_CLAMP));
    float h = an.w * expf(fminf(rg.w, SCALE_CLAMP));
    float x1 = fminf(fmaxf((cx - 0.5f * w) * IMG_INV, 0.0f), 1.0f);
    float y1 = fminf(fmaxf((cy - 0.5f * h) * IMG_INV, 0.0f), 1.0f);
    float x2 = fminf(fmaxf((cx + 0.5f * w) * IMG_INV, 0.0f), 1.0f);
    float y2 = fminf(fmaxf((cy + 0.5f * h) * IMG_INV, 0.0f), 1.0f);

    out[4 * j + 0] = x1; out[4 * j + 1] = y1;
    out[4 * j + 2] = x2; out[4 * j + 3] = y2;
    out[4000 + j] = best;
    out[5000 + j] = (float)bl;
    g_boxes[j] = make_float4(x1, y1, x2, y2);
    g_labels[j] = bl;
    g_valid[j] = (best >= 0.05f) ? 1 : 0;
}

// suppression bitmask: 1000 blocks x 256; mask[i][w] bit b => j=w*32+b sup. i
__global__ void k_mask() {
    int i = blockIdx.x;
    float4 bi = g_boxes[i];
    int li = g_labels[i];
    float ai = (bi.z - bi.x) * (bi.w - bi.y);
    int lane = threadIdx.x & 31, w0 = threadIdx.x >> 5;
    for (int W = w0; W < 32; W += 8) {
        int j = W * 32 + lane;
        bool sup = false;
        if (j < i) {
            if (g_labels[j] == li) {
                float4 bj = g_boxes[j];
                float xx1 = fmaxf(bi.x, bj.x), yy1 = fmaxf(bi.y, bj.y);
                float xx2 = fminf(bi.z, bj.z), yy2 = fminf(bi.w, bj.w);
                float ww = fmaxf(1e-10f, xx2 - xx1);
                float hh = fmaxf(1e-10f, yy2 - yy1);
                float inter = ww * hh;
                float aj = (bj.z - bj.x) * (bj.w - bj.y);
                float iou = inter / (ai + aj - inter + 1e-10f);
                sup = iou > 0.6f;
            }
        }
        unsigned bits = __ballot_sync(0xffffffffu, sup);
        if (lane == 0) g_mask[i * 32 + W] = bits;
    }
}

// serial greedy NMS: 1 block; mask + valid staged in smem; warp 0 runs loop;
// keep bits accumulated in per-lane registers, outputs written once at end.
__global__ void k_nms(float* __restrict__ out) {
    extern __shared__ unsigned sm[];          // [K_TOP*32] mask + [K_TOP] valid
    unsigned* smv = sm + K_TOP * 32;
    for (int idx = threadIdx.x; idx < K_TOP * 32; idx += blockDim.x)
        sm[idx] = g_mask[idx];
    for (int idx = threadIdx.x; idx < K_TOP; idx += blockDim.x)
        smv[idx] = (unsigned)g_valid[idx];
    __syncthreads();
    if (threadIdx.x >= 32) return;
    int t = threadIdx.x;

    unsigned keepw = 0u;
    unsigned cur = sm[t];
    unsigned vcur = smv[0];
    for (int i = 0; i < K_TOP; i++) {
        unsigned nxt  = (i < K_TOP - 1) ? sm[(i + 1) * 32 + t] : 0u;
        unsigned vnxt = (i < K_TOP - 1) ? smv[i + 1] : 0u;
        bool ov = __any_sync(0xffffffffu, (cur & keepw) != 0u);
        bool kp = (vcur != 0u) && !ov;
        if (kp && t == (i >> 5)) keepw |= (1u << (i & 31));
        cur = nxt; vcur = vnxt;
    }
    // write results: lane t owns candidates [t*32, t*32+32)
#pragma unroll
    for (int b = 0; b < 32; b++) {
        int i = t * 32 + b;
        if (i < K_TOP) out[6000 + i] = ((keepw >> b) & 1u) ? 1.0f : 0.0f;
    }
}

// ---------------- launcher ---------------------------------------------------
extern "C" void kernel_launch(void* const* d_in, const int* in_sizes, int n_in,
                              void* d_out, int out_size) {
    const float* cls = (const float*)d_in[0];
    const float* reg = (const float*)d_in[1];
    const float* anc = (const float*)d_in[2];
    float* out = (float*)d_out;

    (void)in_sizes; (void)n_in; (void)out_size;

    cudaFuncSetAttribute(k_nms, cudaFuncAttributeMaxDynamicSharedMemorySize,
                         (K_TOP * 32 + K_TOP) * (int)sizeof(unsigned));

    k_init<<<1, 1024>>>();
    k_rowmax<<<1152, 512>>>(cls);
    k_find1<<<1, 1024>>>();
    k_hist2<<<288, 256>>>();
    k_find2<<<1, 1024>>>();
    k_compact<<<288, 256>>>();
    k_rank<<<8, 512>>>();
    k_decode<<<8, 128>>>(cls, reg, anc, out);
    k_mask<<<1000, 256>>>();
    k_nms<<<1, 1024, (K_TOP * 32 + K_TOP) * sizeof(unsigned)>>>(out);
}